// round 15
// baseline (speedup 1.0000x reference)
#include <cuda_runtime.h>
#include <math.h>

#define BATCH 65536
#define IN_F  2048
#define GROUP 256
#define VEC_ROW (IN_F / 4)        // 512 float4 per row
#define KSTEPS  (VEC_ROW / 32)    // 16 float4 per lane per row
#define NSM 152
#define CHUNK 2                   // rows per work unit (fine-grained: small tail)
#define NCHUNKS (BATCH / CHUNK)   // 32768
#define PF 2                      // prefetch distance (3-stage pipeline)
#define NGROUPS (BATCH / GROUP)   // 256

// float atomic max via signed/unsigned ordering trick (valid for all finite
// floats and -inf init): non-negative -> int max; negative -> uint min.
__device__ __forceinline__ void atomicMaxFloat(float* addr, float v)
{
    if (v >= 0.0f) atomicMax((int*)addr, __float_as_int(v));
    else           atomicMin((unsigned int*)addr, __float_as_uint(v));
}

// -------- Phase 0: init ONLY the 256 group heads to -inf (1 KB) ------------
__global__ __launch_bounds__(NGROUPS)
void init_heads(float* __restrict__ out)
{
    out[threadIdx.x * GROUP] = -INFINITY;
}

// ---------------- Phase 1: persistent GEMV + GELU + atomic group max -------
// CHUNK=2: per-warp work = 215/32 ~ 6.7 units, so the end-of-kernel tail
// (warps with one extra unit) is ~0.26 units at ~72% warp liveness, vs
// CHUNK=4's 0.63 units at ~34% liveness. Keeps DRAM subscribed to the end.
__global__ __launch_bounds__(1024, 1)
void gemv_phase1(const float* __restrict__ x,
                 const float* __restrict__ w,
                 const float* __restrict__ bias,
                 float* __restrict__ out)
{
    __shared__ float4 sw[VEC_ROW];   // 8 KB weight cache

    const int tid  = threadIdx.x;
    const int warp = tid >> 5;
    const int lane = tid & 31;

    if (tid < VEC_ROW) sw[tid] = reinterpret_cast<const float4*>(w)[tid];
    __syncthreads();

    const float b = bias[0];

    // Contiguous chunk span per CTA: 215 or 216 chunks (32768 over 152 CTAs).
    const int per = NCHUNKS / NSM;          // 215
    const int rem = NCHUNKS % NSM;          // 88
    const int bx  = blockIdx.x;
    const int begin = bx * per + (bx < rem ? bx : rem);
    const int count = per + (bx < rem ? 1 : 0);

    for (int ci = warp; ci < count; ci += 32) {
        const int row0 = (begin + ci) * CHUNK;
        const float4* __restrict__ xb =
            reinterpret_cast<const float4*>(x + (size_t)row0 * IN_F) + lane;

        float s0 = 0.f, s1 = 0.f;

        // 3-stage software pipeline over 2 rows: ~6 LDG.128 in flight/warp.
        float4 buf[PF + 1][2];
        #pragma unroll
        for (int p = 0; p < PF; p++) {
            const int off = p * 32;
            buf[p][0] = __ldcs(xb + off);
            buf[p][1] = __ldcs(xb + off + VEC_ROW);
        }

        #pragma unroll
        for (int i = 0; i < KSTEPS; i++) {
            if (i + PF < KSTEPS) {
                const int off = (i + PF) * 32;
                const int st  = (i + PF) % (PF + 1);
                buf[st][0] = __ldcs(xb + off);
                buf[st][1] = __ldcs(xb + off + VEC_ROW);
            }
            const int cu = i % (PF + 1);
            float4 wv = sw[lane + i * 32];
            s0 = fmaf(buf[cu][0].x, wv.x, s0); s0 = fmaf(buf[cu][0].y, wv.y, s0);
            s0 = fmaf(buf[cu][0].z, wv.z, s0); s0 = fmaf(buf[cu][0].w, wv.w, s0);
            s1 = fmaf(buf[cu][1].x, wv.x, s1); s1 = fmaf(buf[cu][1].y, wv.y, s1);
            s1 = fmaf(buf[cu][1].z, wv.z, s1); s1 = fmaf(buf[cu][1].w, wv.w, s1);
        }

        // 2 interleaved butterfly all-reduces.
        #pragma unroll
        for (int o = 16; o > 0; o >>= 1) {
            s0 += __shfl_xor_sync(0xFFFFFFFFu, s0, o);
            s1 += __shfl_xor_sync(0xFFFFFFFFu, s1, o);
        }

        // Epilogue: lanes 0..1 compute the 2 row GELUs; zero-fill non-head
        // rows; one atomicMax per chunk into the group head.
        float v = -INFINITY;
        if (lane < 2) {
            float sum = (lane == 0) ? s0 : s1;
            float p = (sum + b) * 0.25f;
            float inner = 0.7978845608f * (p + 0.044715f * p * p * p);
            float g = 0.5f * p * (1.0f + tanhf(inner));
            v = g * 2.0f;
            const bool isHead = ((row0 & (GROUP - 1)) == 0) && (lane == 0);
            if (!isHead) out[row0 + lane] = 0.0f;
        }
        v = fmaxf(v, __shfl_xor_sync(0xFFFFFFFFu, v, 1));
        if (lane == 0) {
            atomicMaxFloat(&out[row0 & ~(GROUP - 1)], v);
        }
    }
}

extern "C" void kernel_launch(void* const* d_in, const int* in_sizes, int n_in,
                              void* d_out, int out_size)
{
    const float* x    = (const float*)d_in[0];   // [65536, 2048]
    const float* w    = (const float*)d_in[1];   // [1, 2048]
    const float* bias = (const float*)d_in[2];   // [1]
    float* out = (float*)d_out;                  // [65536]

    init_heads<<<1, NGROUPS>>>(out);
    gemv_phase1<<<NSM, 1024>>>(x, w, bias, out);
}

// round 16
// speedup vs baseline: 1.0198x; 1.0198x over previous
#include <cuda_runtime.h>
#include <math.h>

#define BATCH 65536
#define IN_F  2048
#define GROUP 256
#define VEC_ROW (IN_F / 4)        // 512 float4 per row
#define KSTEPS  (VEC_ROW / 32)    // 16 float4 per lane per row
#define NSM 152
#define CHUNK 2                   // rows per work unit (fine-grained: small tail)
#define NCHUNKS (BATCH / CHUNK)   // 32768
#define PF 2                      // prefetch distance (3-stage pipeline)
#define NGROUPS (BATCH / GROUP)   // 256

// float atomic max via signed/unsigned ordering trick (valid for all finite
// floats and -inf init): non-negative -> int max; negative -> uint min.
__device__ __forceinline__ void atomicMaxFloat(float* addr, float v)
{
    if (v >= 0.0f) atomicMax((int*)addr, __float_as_int(v));
    else           atomicMin((unsigned int*)addr, __float_as_uint(v));
}

// -------- Phase 0: init ONLY the 256 group heads to -inf (1 KB) ------------
__global__ __launch_bounds__(NGROUPS)
void init_heads(float* __restrict__ out)
{
    out[threadIdx.x * GROUP] = -INFINITY;
}

// ---------------- Phase 1: persistent GEMV + GELU + atomic group max -------
// CHUNK=2: per-warp work = 215/32 ~ 6.7 units, so the end-of-kernel tail
// (warps with one extra unit) is ~0.26 units at ~72% warp liveness, vs
// CHUNK=4's 0.63 units at ~34% liveness. Keeps DRAM subscribed to the end.
__global__ __launch_bounds__(1024, 1)
void gemv_phase1(const float* __restrict__ x,
                 const float* __restrict__ w,
                 const float* __restrict__ bias,
                 float* __restrict__ out)
{
    __shared__ float4 sw[VEC_ROW];   // 8 KB weight cache

    const int tid  = threadIdx.x;
    const int warp = tid >> 5;
    const int lane = tid & 31;

    if (tid < VEC_ROW) sw[tid] = reinterpret_cast<const float4*>(w)[tid];
    __syncthreads();

    const float b = bias[0];

    // Contiguous chunk span per CTA: 215 or 216 chunks (32768 over 152 CTAs).
    const int per = NCHUNKS / NSM;          // 215
    const int rem = NCHUNKS % NSM;          // 88
    const int bx  = blockIdx.x;
    const int begin = bx * per + (bx < rem ? bx : rem);
    const int count = per + (bx < rem ? 1 : 0);

    for (int ci = warp; ci < count; ci += 32) {
        const int row0 = (begin + ci) * CHUNK;
        const float4* __restrict__ xb =
            reinterpret_cast<const float4*>(x + (size_t)row0 * IN_F) + lane;

        float s0 = 0.f, s1 = 0.f;

        // 3-stage software pipeline over 2 rows: ~6 LDG.128 in flight/warp.
        float4 buf[PF + 1][2];
        #pragma unroll
        for (int p = 0; p < PF; p++) {
            const int off = p * 32;
            buf[p][0] = __ldcs(xb + off);
            buf[p][1] = __ldcs(xb + off + VEC_ROW);
        }

        #pragma unroll
        for (int i = 0; i < KSTEPS; i++) {
            if (i + PF < KSTEPS) {
                const int off = (i + PF) * 32;
                const int st  = (i + PF) % (PF + 1);
                buf[st][0] = __ldcs(xb + off);
                buf[st][1] = __ldcs(xb + off + VEC_ROW);
            }
            const int cu = i % (PF + 1);
            float4 wv = sw[lane + i * 32];
            s0 = fmaf(buf[cu][0].x, wv.x, s0); s0 = fmaf(buf[cu][0].y, wv.y, s0);
            s0 = fmaf(buf[cu][0].z, wv.z, s0); s0 = fmaf(buf[cu][0].w, wv.w, s0);
            s1 = fmaf(buf[cu][1].x, wv.x, s1); s1 = fmaf(buf[cu][1].y, wv.y, s1);
            s1 = fmaf(buf[cu][1].z, wv.z, s1); s1 = fmaf(buf[cu][1].w, wv.w, s1);
        }

        // 2 interleaved butterfly all-reduces.
        #pragma unroll
        for (int o = 16; o > 0; o >>= 1) {
            s0 += __shfl_xor_sync(0xFFFFFFFFu, s0, o);
            s1 += __shfl_xor_sync(0xFFFFFFFFu, s1, o);
        }

        // Epilogue: lanes 0..1 compute the 2 row GELUs; zero-fill non-head
        // rows; one atomicMax per chunk into the group head.
        float v = -INFINITY;
        if (lane < 2) {
            float sum = (lane == 0) ? s0 : s1;
            float p = (sum + b) * 0.25f;
            float inner = 0.7978845608f * (p + 0.044715f * p * p * p);
            float g = 0.5f * p * (1.0f + tanhf(inner));
            v = g * 2.0f;
            const bool isHead = ((row0 & (GROUP - 1)) == 0) && (lane == 0);
            if (!isHead) out[row0 + lane] = 0.0f;
        }
        v = fmaxf(v, __shfl_xor_sync(0xFFFFFFFFu, v, 1));
        if (lane == 0) {
            atomicMaxFloat(&out[row0 & ~(GROUP - 1)], v);
        }
    }
}

extern "C" void kernel_launch(void* const* d_in, const int* in_sizes, int n_in,
                              void* d_out, int out_size)
{
    const float* x    = (const float*)d_in[0];   // [65536, 2048]
    const float* w    = (const float*)d_in[1];   // [1, 2048]
    const float* bias = (const float*)d_in[2];   // [1]
    float* out = (float*)d_out;                  // [65536]

    init_heads<<<1, NGROUPS>>>(out);
    gemv_phase1<<<NSM, 1024>>>(x, w, bias, out);
}